// round 8
// baseline (speedup 1.0000x reference)
#include <cuda_runtime.h>
#include <cuda_fp16.h>
#include <math.h>
#include <stdint.h>

// Problem shape (fixed by dataset)
#define B 4
#define S 2048
#define H 1024
#define NCH 32          // chunks of 64 t per batch
#define CHW 64

// Scratch (device globals: no allocation allowed in kernel_launch)
__device__ __align__(16) __half g_valueh[B * S * H];  // value projection (fp16)
__device__ __align__(16) __half g_Ah[B * S * H];      // hs  as fp16
__device__ __align__(16) __half g_Bh[H * H];          // W   as fp16
__device__ float g_A[B * S];        // (x.U + U_H) / 8   per row
__device__ float g_C[B * S];        // x.V + V_H         per row
__device__ float g_m[B * S];        // row max of scores
__device__ float g_csort[B * S];    // c sorted ascending per batch
__device__ int   g_cperm[B * S];    // original t index per sorted position
__device__ float g_masksort[B * S]; // mask[cperm[j]]
__device__ int   g_sperm[B * S];    // s rows sorted by a per batch
__device__ float g_chmin[B * NCH];
__device__ float g_chmax[B * NCH];
__device__ float g_chmmax[B * NCH];

// ---------------------------------------------------------------------------
// PTX helpers (portable sm_80+ tensor path: cp.async + ldmatrix + mma.sync)
// ---------------------------------------------------------------------------
__device__ __forceinline__ uint32_t smem_u32(const void* p) {
    uint32_t a;
    asm("{ .reg .u64 t; cvta.to.shared.u64 t, %1; cvt.u32.u64 %0, t; }"
        : "=r"(a) : "l"(p));
    return a;
}
#define CPASYNC16(dst, src) \
    asm volatile("cp.async.cg.shared.global [%0], [%1], 16;" :: "r"(dst), "l"(src))
#define CPCOMMIT() asm volatile("cp.async.commit_group;" ::: "memory")
#define CPWAIT2()  asm volatile("cp.async.wait_group 2;" ::: "memory")
#define LDSM4(R, addr)                                                        \
    asm volatile("ldmatrix.sync.aligned.m8n8.x4.shared.b16 {%0,%1,%2,%3}, [%4];" \
                 : "=r"((R)[0]), "=r"((R)[1]), "=r"((R)[2]), "=r"((R)[3])     \
                 : "r"(addr))
#define MMA16816(d, a, b0, b1)                                                \
    asm volatile(                                                             \
        "mma.sync.aligned.m16n8k16.row.col.f32.f16.f16.f32 "                  \
        "{%0,%1,%2,%3}, {%4,%5,%6,%7}, {%8,%9}, {%0,%1,%2,%3};"               \
        : "+f"((d)[0]), "+f"((d)[1]), "+f"((d)[2]), "+f"((d)[3])              \
        : "r"((a)[0]), "r"((a)[1]), "r"((a)[2]), "r"((a)[3]),                 \
          "r"(b0), "r"(b1))

// ---------------------------------------------------------------------------
// Convert: fp32 -> fp16
// ---------------------------------------------------------------------------
__global__ __launch_bounds__(256) void k_convert(
    const float* __restrict__ src, __half* __restrict__ dst, int n4)
{
    int i = blockIdx.x * blockDim.x + threadIdx.x;
    if (i >= n4) return;
    float4 v = ((const float4*)src)[i];
    ((__half2*)dst)[i * 2]     = __floats2half2_rn(v.x, v.y);
    ((__half2*)dst)[i * 2 + 1] = __floats2half2_rn(v.z, v.w);
}

// ---------------------------------------------------------------------------
// K1: fp16 mma.sync GEMM, fp16 output (+bias).  CTA 128x128, 8 warps,
// BK=32, 4-stage cp.async pipeline. Row pitch 80B (conflict-free ldmatrix).
// ---------------------------------------------------------------------------
#define GBK 32
#define NKC (H / GBK)           // 32
#define NSTAGE 4
#define MAT_BYTES (128 * 80)            // 10240 per matrix per stage
#define STG_BYTES (2 * MAT_BYTES)       // A + B
#define GEMM_SMEM (NSTAGE * STG_BYTES)  // 81920

__global__ __launch_bounds__(256, 2) void k_gemm_mma(
    const __half* __restrict__ Ah, const __half* __restrict__ Bh,
    const float* __restrict__ bias, __half* __restrict__ Cout)
{
    extern __shared__ char gsm[];
    const uint32_t smb = smem_u32(gsm);

    const int tid  = threadIdx.x;
    const int wid  = tid >> 5;
    const int lane = tid & 31;
    const int m0   = blockIdx.y * 128;
    const int n0   = blockIdx.x * 128;
    const int wm   = wid & 1;    // 0..1 -> 64 m rows
    const int wn   = wid >> 1;   // 0..3 -> 32 n cols

    const int ldrow = tid >> 2;          // 0..63 (x2 passes -> 128 rows)
    const int ldc   = tid & 3;           // 16B chunk

    float acc[4][4][4];
#pragma unroll
    for (int i = 0; i < 4; i++)
#pragma unroll
        for (int j = 0; j < 4; j++)
#pragma unroll
            for (int q = 0; q < 4; q++) acc[i][j][q] = 0.f;

    auto load_stage = [&](int st, int kc) {
        const int k0 = kc * GBK;
        const uint32_t aB = smb + st * STG_BYTES;
        const uint32_t bB = aB + MAT_BYTES;
#pragma unroll
        for (int r = 0; r < 2; r++) {
            int row = ldrow + r * 64;
            uint32_t off = (uint32_t)row * 80u + (uint32_t)ldc * 16u;
            CPASYNC16(aB + off, Ah + (size_t)(m0 + row) * H + k0 + ldc * 8);
            CPASYNC16(bB + off, Bh + (size_t)(n0 + row) * H + k0 + ldc * 8);
        }
        CPCOMMIT();
    };

#pragma unroll
    for (int st = 0; st < NSTAGE - 1; st++) load_stage(st, st);

    for (int kc = 0; kc < NKC; kc++) {
        const int st = kc & (NSTAGE - 1);
        CPWAIT2();
        __syncthreads();

        const int nk = kc + NSTAGE - 1;
        if (nk < NKC) load_stage(nk & (NSTAGE - 1), nk);
        else          CPCOMMIT();

        const uint32_t aw = smb + st * STG_BYTES + (wm * 64) * 80;
        const uint32_t bw = smb + st * STG_BYTES + MAT_BYTES + (wn * 32) * 80;
        const uint32_t lrow = (lane & 15);
        const uint32_t lcol = (lane >> 4) * 16;   // byte offset for k-half

#pragma unroll
        for (int ks = 0; ks < 2; ks++) {
            const uint32_t kb = ks * 32 + lcol;
            uint32_t a[4][4];
#pragma unroll
            for (int i = 0; i < 4; i++)
                LDSM4(a[i], aw + (i * 16 + lrow) * 80 + kb);
            uint32_t br[2][4];
#pragma unroll
            for (int jj = 0; jj < 2; jj++)
                LDSM4(br[jj], bw + (jj * 16 + lrow) * 80 + kb);
#pragma unroll
            for (int i = 0; i < 4; i++) {
                MMA16816(acc[i][0], a[i], br[0][0], br[0][2]);
                MMA16816(acc[i][1], a[i], br[0][1], br[0][3]);
                MMA16816(acc[i][2], a[i], br[1][0], br[1][2]);
                MMA16816(acc[i][3], a[i], br[1][1], br[1][3]);
            }
        }
    }

    // Epilogue: fp16 stores with bias
#pragma unroll
    for (int j = 0; j < 4; j++) {
        int col = n0 + wn * 32 + j * 8 + (lane & 3) * 2;
        float b0 = bias[col], b1 = bias[col + 1];
#pragma unroll
        for (int i = 0; i < 4; i++) {
            int row = m0 + wm * 64 + i * 16 + (lane >> 2);
            *(__half2*)(Cout + (size_t)row * H + col) =
                __floats2half2_rn(acc[i][j][0] + b0, acc[i][j][1] + b1);
            *(__half2*)(Cout + (size_t)(row + 8) * H + col) =
                __floats2half2_rn(acc[i][j][2] + b0, acc[i][j][3] + b1);
        }
    }
}

// ---------------------------------------------------------------------------
// K2: per-row rank-1 projections, warp per row
// ---------------------------------------------------------------------------
__global__ __launch_bounds__(256) void k_proj(
    const float* __restrict__ hs, const float* __restrict__ U,
    const float* __restrict__ Vm)
{
    const int row  = blockIdx.x * 8 + (threadIdx.x >> 5);
    const int lane = threadIdx.x & 31;
    const float4* x4 = (const float4*)(hs + (size_t)row * H);
    const float4* u4 = (const float4*)U;
    const float4* v4 = (const float4*)Vm;
    float su = 0.f, sv = 0.f;
#pragma unroll
    for (int i = 0; i < 8; i++) {
        int j = i * 32 + lane;
        float4 x = x4[j], u = u4[j], v = v4[j];
        su += x.x * u.x + x.y * u.y + x.z * u.z + x.w * u.w;
        sv += x.x * v.x + x.y * v.y + x.z * v.z + x.w * v.w;
    }
#pragma unroll
    for (int o = 16; o > 0; o >>= 1) {
        su += __shfl_xor_sync(0xFFFFFFFFu, su, o);
        sv += __shfl_xor_sync(0xFFFFFFFFu, sv, o);
    }
    if (lane == 0) {
        g_A[row] = (su + U[H]) * 0.125f;
        g_C[row] = sv + Vm[H];
    }
}

// ---------------------------------------------------------------------------
// Bitonic sort: 2048 (key, idx) pairs ascending, one block.
// ---------------------------------------------------------------------------
__device__ __forceinline__ void bitonic_sort_2048(float* key, int* idx)
{
    for (int k = 2; k <= 2048; k <<= 1) {
        for (int j = k >> 1; j > 0; j >>= 1) {
#pragma unroll
            for (int p = 0; p < 2; p++) {
                int i = threadIdx.x + p * 1024;
                int l = i ^ j;
                if (l > i) {
                    bool up = ((i & k) == 0);
                    float ki = key[i], kl = key[l];
                    bool sw = up ? (ki > kl) : (ki < kl);
                    if (sw) {
                        key[i] = kl; key[l] = ki;
                        int t = idx[i]; idx[i] = idx[l]; idx[l] = t;
                    }
                }
            }
            __syncthreads();
        }
    }
}

__global__ __launch_bounds__(1024) void k_sort_c(const float* __restrict__ mask)
{
    const int b = blockIdx.x;
    __shared__ float key[2048];
    __shared__ int   idx[2048];
    for (int i = threadIdx.x; i < 2048; i += 1024) { key[i] = g_C[b * S + i]; idx[i] = i; }
    __syncthreads();
    bitonic_sort_2048(key, idx);
    for (int i = threadIdx.x; i < 2048; i += 1024) {
        g_csort[b * S + i]    = key[i];
        g_cperm[b * S + i]    = idx[i];
        g_masksort[b * S + i] = mask[b * S + idx[i]];
    }
    __syncthreads();
    if (threadIdx.x < NCH) {
        int ch = threadIdx.x;
        float mm = -INFINITY;
        for (int j = 0; j < CHW; j++)
            mm = fmaxf(mm, mask[b * S + idx[ch * CHW + j]]);
        g_chmin[b * NCH + ch]  = key[ch * CHW];
        g_chmax[b * NCH + ch]  = key[ch * CHW + CHW - 1];
        g_chmmax[b * NCH + ch] = mm;
    }
}

__global__ __launch_bounds__(1024) void k_sort_a()
{
    const int b = blockIdx.x;
    __shared__ float key[2048];
    __shared__ int   idx[2048];
    for (int i = threadIdx.x; i < 2048; i += 1024) { key[i] = g_A[b * S + i]; idx[i] = i; }
    __syncthreads();
    bitonic_sort_2048(key, idx);
    for (int i = threadIdx.x; i < 2048; i += 1024) g_sperm[b * S + i] = idx[i];
}

// ---------------------------------------------------------------------------
// K3: exact row max m = max_t (a*c_t + mask_t).  Warp per row.
// ---------------------------------------------------------------------------
__global__ __launch_bounds__(256) void k_max(const float* __restrict__ mask)
{
    const int row  = blockIdx.x * 8 + (threadIdx.x >> 5);
    const int b    = row >> 11;
    const int lane = threadIdx.x & 31;
    const float a  = g_A[row];
    const float* c  = g_C + (b << 11);
    const float* mk = mask + (b << 11);
    float m = -INFINITY;
    for (int t = lane; t < S; t += 32)
        m = fmaxf(m, fmaf(a, c[t], mk[t]));
#pragma unroll
    for (int o = 16; o > 0; o >>= 1)
        m = fmaxf(m, __shfl_xor_sync(0xFFFFFFFFu, m, o));
    if (lane == 0) g_m[row] = m;
}

// ---------------------------------------------------------------------------
// K4: sparse context (16 a-sorted s rows x full H).
//  - skip inactive c-chunks (upper bound test, threshold -20)
//  - within active chunks, compact to t-columns live for at least one row
//  - value read as fp16, accumulate fp32
// ---------------------------------------------------------------------------
#define STILE 16
__global__ __launch_bounds__(256) void k_context_sparse(float* __restrict__ out)
{
    const int b   = blockIdx.y;
    const int tid = threadIdx.x;

    __shared__ float wts[STILE][CHW];
    __shared__ float csh[CHW], msh[CHW];
    __shared__ int   psh[CHW];
    __shared__ int   actlist[CHW];
    __shared__ int   nact;
    __shared__ float As[STILE], Ms[STILE], Zs[STILE];
    __shared__ int   rowid[STILE];
    __shared__ unsigned actmask;

    if (tid < STILE) {
        int srow = g_sperm[b * S + blockIdx.x * STILE + tid];
        rowid[tid] = srow;
        As[tid] = g_A[b * S + srow];
        Ms[tid] = g_m[b * S + srow];
        Zs[tid] = 0.f;
    }

    float4 acc[STILE];
#pragma unroll
    for (int i = 0; i < STILE; i++) acc[i] = make_float4(0.f, 0.f, 0.f, 0.f);

    for (int ch = 0; ch < NCH; ch++) {
        __syncthreads();
        if (tid == 0) { actmask = 0; nact = 0; }
        __syncthreads();
        if (tid < STILE) {
            float a = As[tid];
            float cext = (a > 0.f) ? g_chmax[b * NCH + ch] : g_chmin[b * NCH + ch];
            float ub = fmaf(a, cext, g_chmmax[b * NCH + ch]) - Ms[tid];
            if (ub > -20.f) atomicOr(&actmask, 1u << tid);
        }
        __syncthreads();
        if (actmask == 0) continue;

        if (tid < CHW) {
            int g = b * S + ch * CHW + tid;
            csh[tid] = g_csort[g];
            msh[tid] = g_masksort[g];
            psh[tid] = g_cperm[g];
        }
        __syncthreads();

        // weights: 16 x 64 entries, 4 per thread
#pragma unroll
        for (int i = 0; i < (STILE * CHW) / 256; i++) {
            int idx = tid + i * 256;
            int si  = idx >> 6;
            int tj  = idx & (CHW - 1);
            float sc = fmaf(As[si], csh[tj], msh[tj]) - Ms[si];
            wts[si][tj] = (sc > -25.f) ? __expf(sc) : 0.f;
        }
        __syncthreads();

        // per-row Z and live-column compaction
        if (tid < STILE) {
            float z = 0.f;
#pragma unroll 8
            for (int j = 0; j < CHW; j++) z += wts[tid][j];
            Zs[tid] += z;
        } else if (tid >= 64 && tid < 64 + CHW) {
            int tj = tid - 64;
            float cm = 0.f;
#pragma unroll
            for (int si = 0; si < STILE; si++) cm = fmaxf(cm, wts[si][tj]);
            if (cm > 0.f) { int p = atomicAdd(&nact, 1); actlist[p] = tj; }
        }
        __syncthreads();

        const int na = nact;
        for (int j = 0; j < na; j++) {
            const int tj = actlist[j];
            const uint2 hv = *((const uint2*)(g_valueh +
                               (((size_t)(b * S) + psh[tj]) << 10)) + tid);
            float2 v01 = __half22float2(*(const __half2*)&hv.x);
            float2 v23 = __half22float2(*(const __half2*)&hv.y);
#pragma unroll
            for (int si = 0; si < STILE; si++) {
                float w = wts[si][tj];
                acc[si].x += w * v01.x;
                acc[si].y += w * v01.y;
                acc[si].z += w * v23.x;
                acc[si].w += w * v23.y;
            }
        }
    }
    __syncthreads();

#pragma unroll
    for (int si = 0; si < STILE; si++) {
        float iz = 1.f / Zs[si];
        size_t o = (((size_t)(b * S) + rowid[si]) << 10) + tid * 4;
        *(float4*)(out + o) = make_float4(acc[si].x * iz, acc[si].y * iz,
                                          acc[si].z * iz, acc[si].w * iz);
    }
}

// ---------------------------------------------------------------------------
extern "C" void kernel_launch(void* const* d_in, const int* in_sizes, int n_in,
                              void* d_out, int out_size)
{
    const float* hs    = (const float*)d_in[0];  // [B,S,H]
    const float* mask  = (const float*)d_in[1];  // [B,S]
    const float* wv    = (const float*)d_in[2];  // [H,H]
    const float* bv    = (const float*)d_in[3];  // [H]
    const float* U     = (const float*)d_in[4];  // [H+1,1]
    const float* Vm    = (const float*)d_in[5];  // [1,H+1]
    float* out         = (float*)d_out;          // [B,S,H]

    __half* vproj = nullptr;
    cudaGetSymbolAddress((void**)&vproj, g_valueh);
    __half* ah = nullptr;
    cudaGetSymbolAddress((void**)&ah, g_Ah);
    __half* bh = nullptr;
    cudaGetSymbolAddress((void**)&bh, g_Bh);

    // fp16 conversions
    k_convert<<<(B * S * (H / 4) + 255) / 256, 256>>>(hs, ah, B * S * (H / 4));
    k_convert<<<(H * (H / 4) + 255) / 256, 256>>>(wv, bh, H * (H / 4));

    // K1: value projection via fp16 mma.sync (fp32 accumulate, fp16 out)
    cudaFuncSetAttribute(k_gemm_mma, cudaFuncAttributeMaxDynamicSharedMemorySize,
                         GEMM_SMEM);
    {
        dim3 grid(H / 128, (B * S) / 128);
        k_gemm_mma<<<grid, 256, GEMM_SMEM>>>(ah, bh, bv, vproj);
    }
    // K2: rank-1 projections a, c
    k_proj<<<B * S / 8, 256>>>(hs, U, Vm);
    // sorts + row maxima
    k_sort_c<<<B, 1024>>>(mask);
    k_sort_a<<<B, 1024>>>();
    k_max<<<(B * S) / 8, 256>>>(mask);
    // K4: sparse context
    {
        dim3 grid(S / STILE, B);
        k_context_sparse<<<grid, 256>>>(out);
    }
}

// round 9
// speedup vs baseline: 1.5947x; 1.5947x over previous
#include <cuda_runtime.h>
#include <cuda_fp16.h>
#include <math.h>
#include <stdint.h>

// Problem shape (fixed by dataset)
#define B 4
#define S 2048
#define H 1024
#define NCH 32          // chunks of 64 t per batch
#define CHW 64

// Scratch (device globals: no allocation allowed in kernel_launch)
__device__ __align__(16) __half g_valueh[B * S * H];  // value projection (fp16)
__device__ __align__(16) __half g_Ah[B * S * H];      // hs  as fp16
__device__ __align__(16) __half g_Bh[H * H];          // W   as fp16
__device__ float g_A[B * S];        // (x.U + U_H) / 8   per row
__device__ float g_C[B * S];        // x.V + V_H         per row
__device__ float g_m[B * S];        // row max of scores
__device__ float g_csort[B * S];    // c sorted ascending per batch
__device__ int   g_cperm[B * S];    // original t index per sorted position
__device__ float g_masksort[B * S]; // mask[cperm[j]]
__device__ int   g_sperm[B * S];    // s rows sorted by a per batch
__device__ float g_chmin[B * NCH];
__device__ float g_chmax[B * NCH];
__device__ float g_chmmax[B * NCH];

// ---------------------------------------------------------------------------
// PTX helpers (portable sm_80+ tensor path: cp.async + ldmatrix + mma.sync)
// ---------------------------------------------------------------------------
__device__ __forceinline__ uint32_t smem_u32(const void* p) {
    uint32_t a;
    asm("{ .reg .u64 t; cvta.to.shared.u64 t, %1; cvt.u32.u64 %0, t; }"
        : "=r"(a) : "l"(p));
    return a;
}
#define CPASYNC16(dst, src) \
    asm volatile("cp.async.cg.shared.global [%0], [%1], 16;" :: "r"(dst), "l"(src))
#define CPCOMMIT() asm volatile("cp.async.commit_group;" ::: "memory")
#define CPWAIT2()  asm volatile("cp.async.wait_group 2;" ::: "memory")
#define LDSM4(R, addr)                                                        \
    asm volatile("ldmatrix.sync.aligned.m8n8.x4.shared.b16 {%0,%1,%2,%3}, [%4];" \
                 : "=r"((R)[0]), "=r"((R)[1]), "=r"((R)[2]), "=r"((R)[3])     \
                 : "r"(addr))
#define MMA16816(d, a, b0, b1)                                                \
    asm volatile(                                                             \
        "mma.sync.aligned.m16n8k16.row.col.f32.f16.f16.f32 "                  \
        "{%0,%1,%2,%3}, {%4,%5,%6,%7}, {%8,%9}, {%0,%1,%2,%3};"               \
        : "+f"((d)[0]), "+f"((d)[1]), "+f"((d)[2]), "+f"((d)[3])              \
        : "r"((a)[0]), "r"((a)[1]), "r"((a)[2]), "r"((a)[3]),                 \
          "r"(b0), "r"(b1))

// ---------------------------------------------------------------------------
// Convert: fp32 -> fp16
// ---------------------------------------------------------------------------
__global__ __launch_bounds__(256) void k_convert(
    const float* __restrict__ src, __half* __restrict__ dst, int n4)
{
    int i = blockIdx.x * blockDim.x + threadIdx.x;
    if (i >= n4) return;
    float4 v = ((const float4*)src)[i];
    ((__half2*)dst)[i * 2]     = __floats2half2_rn(v.x, v.y);
    ((__half2*)dst)[i * 2 + 1] = __floats2half2_rn(v.z, v.w);
}

// ---------------------------------------------------------------------------
// K1: fp16 mma.sync GEMM, fp16 output (+bias).  CTA 128x128, 8 warps,
// BK=32, 4-stage cp.async pipeline. Row pitch 80B (conflict-free ldmatrix).
// ---------------------------------------------------------------------------
#define GBK 32
#define NKC (H / GBK)           // 32
#define NSTAGE 4
#define MAT_BYTES (128 * 80)            // 10240 per matrix per stage
#define STG_BYTES (2 * MAT_BYTES)       // A + B
#define GEMM_SMEM (NSTAGE * STG_BYTES)  // 81920

__global__ __launch_bounds__(256, 2) void k_gemm_mma(
    const __half* __restrict__ Ah, const __half* __restrict__ Bh,
    const float* __restrict__ bias, __half* __restrict__ Cout)
{
    extern __shared__ char gsm[];
    const uint32_t smb = smem_u32(gsm);

    const int tid  = threadIdx.x;
    const int wid  = tid >> 5;
    const int lane = tid & 31;
    const int m0   = blockIdx.y * 128;
    const int n0   = blockIdx.x * 128;
    const int wm   = wid & 1;    // 0..1 -> 64 m rows
    const int wn   = wid >> 1;   // 0..3 -> 32 n cols

    const int ldrow = tid >> 2;          // 0..63 (x2 passes -> 128 rows)
    const int ldc   = tid & 3;           // 16B chunk

    float acc[4][4][4];
#pragma unroll
    for (int i = 0; i < 4; i++)
#pragma unroll
        for (int j = 0; j < 4; j++)
#pragma unroll
            for (int q = 0; q < 4; q++) acc[i][j][q] = 0.f;

    auto load_stage = [&](int st, int kc) {
        const int k0 = kc * GBK;
        const uint32_t aB = smb + st * STG_BYTES;
        const uint32_t bB = aB + MAT_BYTES;
#pragma unroll
        for (int r = 0; r < 2; r++) {
            int row = ldrow + r * 64;
            uint32_t off = (uint32_t)row * 80u + (uint32_t)ldc * 16u;
            CPASYNC16(aB + off, Ah + (size_t)(m0 + row) * H + k0 + ldc * 8);
            CPASYNC16(bB + off, Bh + (size_t)(n0 + row) * H + k0 + ldc * 8);
        }
        CPCOMMIT();
    };

#pragma unroll
    for (int st = 0; st < NSTAGE - 1; st++) load_stage(st, st);

    for (int kc = 0; kc < NKC; kc++) {
        const int st = kc & (NSTAGE - 1);
        CPWAIT2();
        __syncthreads();

        const int nk = kc + NSTAGE - 1;
        if (nk < NKC) load_stage(nk & (NSTAGE - 1), nk);
        else          CPCOMMIT();

        const uint32_t aw = smb + st * STG_BYTES + (wm * 64) * 80;
        const uint32_t bw = smb + st * STG_BYTES + MAT_BYTES + (wn * 32) * 80;
        const uint32_t lrow = (lane & 15);
        const uint32_t lcol = (lane >> 4) * 16;   // byte offset for k-half

#pragma unroll
        for (int ks = 0; ks < 2; ks++) {
            const uint32_t kb = ks * 32 + lcol;
            uint32_t a[4][4];
#pragma unroll
            for (int i = 0; i < 4; i++)
                LDSM4(a[i], aw + (i * 16 + lrow) * 80 + kb);
            uint32_t br[2][4];
#pragma unroll
            for (int jj = 0; jj < 2; jj++)
                LDSM4(br[jj], bw + (jj * 16 + lrow) * 80 + kb);
#pragma unroll
            for (int i = 0; i < 4; i++) {
                MMA16816(acc[i][0], a[i], br[0][0], br[0][2]);
                MMA16816(acc[i][1], a[i], br[0][1], br[0][3]);
                MMA16816(acc[i][2], a[i], br[1][0], br[1][2]);
                MMA16816(acc[i][3], a[i], br[1][1], br[1][3]);
            }
        }
    }

    // Epilogue: fp16 stores with bias
#pragma unroll
    for (int j = 0; j < 4; j++) {
        int col = n0 + wn * 32 + j * 8 + (lane & 3) * 2;
        float b0 = bias[col], b1 = bias[col + 1];
#pragma unroll
        for (int i = 0; i < 4; i++) {
            int row = m0 + wm * 64 + i * 16 + (lane >> 2);
            *(__half2*)(Cout + (size_t)row * H + col) =
                __floats2half2_rn(acc[i][j][0] + b0, acc[i][j][1] + b1);
            *(__half2*)(Cout + (size_t)(row + 8) * H + col) =
                __floats2half2_rn(acc[i][j][2] + b0, acc[i][j][3] + b1);
        }
    }
}

// ---------------------------------------------------------------------------
// K2: per-row rank-1 projections, warp per row
// ---------------------------------------------------------------------------
__global__ __launch_bounds__(256) void k_proj(
    const float* __restrict__ hs, const float* __restrict__ U,
    const float* __restrict__ Vm)
{
    const int row  = blockIdx.x * 8 + (threadIdx.x >> 5);
    const int lane = threadIdx.x & 31;
    const float4* x4 = (const float4*)(hs + (size_t)row * H);
    const float4* u4 = (const float4*)U;
    const float4* v4 = (const float4*)Vm;
    float su = 0.f, sv = 0.f;
#pragma unroll
    for (int i = 0; i < 8; i++) {
        int j = i * 32 + lane;
        float4 x = x4[j], u = u4[j], v = v4[j];
        su += x.x * u.x + x.y * u.y + x.z * u.z + x.w * u.w;
        sv += x.x * v.x + x.y * v.y + x.z * v.z + x.w * v.w;
    }
#pragma unroll
    for (int o = 16; o > 0; o >>= 1) {
        su += __shfl_xor_sync(0xFFFFFFFFu, su, o);
        sv += __shfl_xor_sync(0xFFFFFFFFu, sv, o);
    }
    if (lane == 0) {
        g_A[row] = (su + U[H]) * 0.125f;
        g_C[row] = sv + Vm[H];
    }
}

// ---------------------------------------------------------------------------
// Bitonic sort: 2048 (key, idx) pairs ascending, one block.
// ---------------------------------------------------------------------------
__device__ __forceinline__ void bitonic_sort_2048(float* key, int* idx)
{
    for (int k = 2; k <= 2048; k <<= 1) {
        for (int j = k >> 1; j > 0; j >>= 1) {
#pragma unroll
            for (int p = 0; p < 2; p++) {
                int i = threadIdx.x + p * 1024;
                int l = i ^ j;
                if (l > i) {
                    bool up = ((i & k) == 0);
                    float ki = key[i], kl = key[l];
                    bool sw = up ? (ki > kl) : (ki < kl);
                    if (sw) {
                        key[i] = kl; key[l] = ki;
                        int t = idx[i]; idx[i] = idx[l]; idx[l] = t;
                    }
                }
            }
            __syncthreads();
        }
    }
}

__global__ __launch_bounds__(1024) void k_sort_c(const float* __restrict__ mask)
{
    const int b = blockIdx.x;
    __shared__ float key[2048];
    __shared__ int   idx[2048];
    for (int i = threadIdx.x; i < 2048; i += 1024) { key[i] = g_C[b * S + i]; idx[i] = i; }
    __syncthreads();
    bitonic_sort_2048(key, idx);
    for (int i = threadIdx.x; i < 2048; i += 1024) {
        g_csort[b * S + i]    = key[i];
        g_cperm[b * S + i]    = idx[i];
        g_masksort[b * S + i] = mask[b * S + idx[i]];
    }
    __syncthreads();
    if (threadIdx.x < NCH) {
        int ch = threadIdx.x;
        float mm = -INFINITY;
        for (int j = 0; j < CHW; j++)
            mm = fmaxf(mm, mask[b * S + idx[ch * CHW + j]]);
        g_chmin[b * NCH + ch]  = key[ch * CHW];
        g_chmax[b * NCH + ch]  = key[ch * CHW + CHW - 1];
        g_chmmax[b * NCH + ch] = mm;
    }
}

__global__ __launch_bounds__(1024) void k_sort_a()
{
    const int b = blockIdx.x;
    __shared__ float key[2048];
    __shared__ int   idx[2048];
    for (int i = threadIdx.x; i < 2048; i += 1024) { key[i] = g_A[b * S + i]; idx[i] = i; }
    __syncthreads();
    bitonic_sort_2048(key, idx);
    for (int i = threadIdx.x; i < 2048; i += 1024) g_sperm[b * S + i] = idx[i];
}

// ---------------------------------------------------------------------------
// K3: exact row max m = max_t (a*c_t + mask_t).  Warp per row.
// ---------------------------------------------------------------------------
__global__ __launch_bounds__(256) void k_max(const float* __restrict__ mask)
{
    const int row  = blockIdx.x * 8 + (threadIdx.x >> 5);
    const int b    = row >> 11;
    const int lane = threadIdx.x & 31;
    const float a  = g_A[row];
    const float* c  = g_C + (b << 11);
    const float* mk = mask + (b << 11);
    float m = -INFINITY;
    for (int t = lane; t < S; t += 32)
        m = fmaxf(m, fmaf(a, c[t], mk[t]));
#pragma unroll
    for (int o = 16; o > 0; o >>= 1)
        m = fmaxf(m, __shfl_xor_sync(0xFFFFFFFFu, m, o));
    if (lane == 0) g_m[row] = m;
}

// ---------------------------------------------------------------------------
// K4: sparse context (16 a-sorted s rows x full H; skip inactive c-chunks).
// Dense unrolled 64-column accumulation within active chunks (high MLP);
// value read as fp16 (uint2), accumulate fp32.
// ---------------------------------------------------------------------------
#define STILE 16
__global__ __launch_bounds__(256) void k_context_sparse(float* __restrict__ out)
{
    const int b   = blockIdx.y;
    const int tid = threadIdx.x;

    __shared__ float wts[STILE][CHW];
    __shared__ float csh[CHW], msh[CHW];
    __shared__ int   psh[CHW];
    __shared__ float As[STILE], Ms[STILE], Zs[STILE];
    __shared__ int   rowid[STILE];
    __shared__ unsigned actmask;

    if (tid < STILE) {
        int srow = g_sperm[b * S + blockIdx.x * STILE + tid];
        rowid[tid] = srow;
        As[tid] = g_A[b * S + srow];
        Ms[tid] = g_m[b * S + srow];
        Zs[tid] = 0.f;
    }

    float4 acc[STILE];
#pragma unroll
    for (int i = 0; i < STILE; i++) acc[i] = make_float4(0.f, 0.f, 0.f, 0.f);

    for (int ch = 0; ch < NCH; ch++) {
        __syncthreads();
        if (tid == 0) actmask = 0;
        __syncthreads();
        if (tid < STILE) {
            float a = As[tid];
            float cext = (a > 0.f) ? g_chmax[b * NCH + ch] : g_chmin[b * NCH + ch];
            float ub = fmaf(a, cext, g_chmmax[b * NCH + ch]) - Ms[tid];
            if (ub > -20.f) atomicOr(&actmask, 1u << tid);
        }
        __syncthreads();
        if (actmask == 0) continue;

        if (tid < CHW) {
            int g = b * S + ch * CHW + tid;
            csh[tid] = g_csort[g];
            msh[tid] = g_masksort[g];
            psh[tid] = g_cperm[g];
        }
        __syncthreads();

#pragma unroll
        for (int i = 0; i < (STILE * CHW) / 256; i++) {
            int idx = tid + i * 256;
            int si  = idx >> 6;
            int tj  = idx & (CHW - 1);
            float sc = fmaf(As[si], csh[tj], msh[tj]) - Ms[si];
            wts[si][tj] = (sc > -25.f) ? __expf(sc) : 0.f;
        }
        __syncthreads();

        if (tid < STILE) {
            float z = 0.f;
#pragma unroll 8
            for (int j = 0; j < CHW; j++) z += wts[tid][j];
            Zs[tid] += z;
        }

        // dense accumulation: static trip count, predictable addresses
#pragma unroll 4
        for (int tj = 0; tj < CHW; tj++) {
            const uint2 hv = *((const uint2*)(g_valueh +
                               (((size_t)(b * S) + psh[tj]) << 10)) + tid);
            float2 v01 = __half22float2(*(const __half2*)&hv.x);
            float2 v23 = __half22float2(*(const __half2*)&hv.y);
#pragma unroll
            for (int si = 0; si < STILE; si++) {
                float w = wts[si][tj];
                acc[si].x += w * v01.x;
                acc[si].y += w * v01.y;
                acc[si].z += w * v23.x;
                acc[si].w += w * v23.y;
            }
        }
    }
    __syncthreads();

#pragma unroll
    for (int si = 0; si < STILE; si++) {
        float iz = 1.f / Zs[si];
        size_t o = (((size_t)(b * S) + rowid[si]) << 10) + tid * 4;
        *(float4*)(out + o) = make_float4(acc[si].x * iz, acc[si].y * iz,
                                          acc[si].z * iz, acc[si].w * iz);
    }
}

// ---------------------------------------------------------------------------
extern "C" void kernel_launch(void* const* d_in, const int* in_sizes, int n_in,
                              void* d_out, int out_size)
{
    const float* hs    = (const float*)d_in[0];  // [B,S,H]
    const float* mask  = (const float*)d_in[1];  // [B,S]
    const float* wv    = (const float*)d_in[2];  // [H,H]
    const float* bv    = (const float*)d_in[3];  // [H]
    const float* U     = (const float*)d_in[4];  // [H+1,1]
    const float* Vm    = (const float*)d_in[5];  // [1,H+1]
    float* out         = (float*)d_out;          // [B,S,H]

    __half* vproj = nullptr;
    cudaGetSymbolAddress((void**)&vproj, g_valueh);
    __half* ah = nullptr;
    cudaGetSymbolAddress((void**)&ah, g_Ah);
    __half* bh = nullptr;
    cudaGetSymbolAddress((void**)&bh, g_Bh);

    // fp16 conversions
    k_convert<<<(B * S * (H / 4) + 255) / 256, 256>>>(hs, ah, B * S * (H / 4));
    k_convert<<<(H * (H / 4) + 255) / 256, 256>>>(wv, bh, H * (H / 4));

    // K1: value projection via fp16 mma.sync (fp32 accumulate, fp16 out)
    cudaFuncSetAttribute(k_gemm_mma, cudaFuncAttributeMaxDynamicSharedMemorySize,
                         GEMM_SMEM);
    {
        dim3 grid(H / 128, (B * S) / 128);
        k_gemm_mma<<<grid, 256, GEMM_SMEM>>>(ah, bh, bv, vproj);
    }
    // K2: rank-1 projections a, c
    k_proj<<<B * S / 8, 256>>>(hs, U, Vm);
    // sorts + row maxima
    k_sort_c<<<B, 1024>>>(mask);
    k_sort_a<<<B, 1024>>>();
    k_max<<<(B * S) / 8, 256>>>(mask);
    // K4: sparse context
    {
        dim3 grid(S / STILE, B);
        k_context_sparse<<<grid, 256>>>(out);
    }
}